// round 1
// baseline (speedup 1.0000x reference)
#include <cuda_runtime.h>

#define N_TOKENS 32768
#define D_MODEL  1024
#define BM 128
#define BN 128
#define BK 16
#define NTHREADS 256

// ---------------- device-global scratch (no allocations allowed) -------------
__device__ int g_cnt0;
__device__ int g_c0;
__device__ int g_c1;
__device__ int g_perm[N_TOKENS];

// ---------------- sort-by-expert pipeline ------------------------------------
__global__ void k_reset() { g_cnt0 = 0; }

__global__ void k_count(const int* __restrict__ route) {
    __shared__ int ws[8];
    int i = blockIdx.x * blockDim.x + threadIdx.x;
    int v = (route[i] == 0) ? 1 : 0;
    #pragma unroll
    for (int o = 16; o > 0; o >>= 1) v += __shfl_down_sync(0xffffffffu, v, o);
    int lane = threadIdx.x & 31, w = threadIdx.x >> 5;
    if (lane == 0) ws[w] = v;
    __syncthreads();
    if (threadIdx.x == 0) {
        int s = 0;
        #pragma unroll
        for (int j = 0; j < 8; j++) s += ws[j];
        atomicAdd(&g_cnt0, s);
    }
}

__global__ void k_init() { g_c0 = 0; g_c1 = g_cnt0; }

__global__ void k_scatter(const int* __restrict__ route) {
    int i = blockIdx.x * blockDim.x + threadIdx.x;
    int slot;
    if (route[i] == 0) slot = atomicAdd(&g_c0, 1);   // warp-aggregated by ptxas
    else               slot = atomicAdd(&g_c1, 1);
    g_perm[slot] = i;
}

// ---------------- packed f32x2 FMA helpers -----------------------------------
#define FMA_F32X2(d, a, b, c) \
    asm("fma.rn.f32x2 %0, %1, %2, %3;" : "=l"(d) : "l"(a), "l"(b), "l"(c))

__device__ __forceinline__ unsigned long long pack_dup(float a) {
    unsigned long long p;
    unsigned int u = __float_as_uint(a);
    asm("mov.b64 %0, {%1, %1};" : "=l"(p) : "r"(u));
    return p;
}

// ---------------- GEMM: rows gathered via perm, W selected per tile ----------
__global__ __launch_bounds__(NTHREADS)
void k_gemm(const float* __restrict__ x,
            const float* __restrict__ W1, const float* __restrict__ b1,
            const float* __restrict__ W2, const float* __restrict__ b2,
            const int* __restrict__ route,
            float* __restrict__ out)
{
    __shared__ __align__(16) float As[BK][BM];
    __shared__ __align__(16) float Bs[2][BK][BN];
    __shared__ int srow[BM];
    __shared__ int srt[BM];

    const int bn  = blockIdx.x * BN;
    const int bm  = blockIdx.y * BM;
    const int tid = threadIdx.x;

    if (tid < BM) {
        int r = g_perm[bm + tid];
        srow[tid] = r;
        srt[tid]  = route[r];
    }
    __syncthreads();

    const int uni = (srt[0] == srt[BM - 1]) ? srt[0] : -1;

    const int tx = tid & 15;   // n-tile index (8 cols each)
    const int ty = tid >> 4;   // m-tile index (8 rows each)

    int myrow[8], myrt[8];
    #pragma unroll
    for (int i = 0; i < 8; i++) { myrow[i] = srow[ty * 8 + i]; myrt[i] = srt[ty * 8 + i]; }

    // packed accumulators: c2[m][n4] holds output cols (2*n4, 2*n4+1) of row m
    unsigned long long c2[8][4];
    #pragma unroll
    for (int m = 0; m < 8; m++)
        #pragma unroll
        for (int n = 0; n < 4; n++) c2[m][n] = 0ull;

    // A-load mapping: thread covers row (tid&127), float4 cols {(tid>>7), (tid>>7)+2}
    const int   arow = tid & 127;
    const float* xrow = x + (size_t)srow[arow] * D_MODEL;
    // B-load mapping: (k-row, float4-col) = (tid>>5 (+8), tid&31)
    const int bkr = tid >> 5;
    const int bc4 = tid & 31;

    for (int kt = 0; kt < D_MODEL; kt += BK) {
        // stage A (transposed: As[k][m])
        #pragma unroll
        for (int l = 0; l < 2; l++) {
            int c4 = (tid >> 7) + 2 * l;
            float4 v = *(const float4*)(xrow + kt + c4 * 4);
            As[c4 * 4 + 0][arow] = v.x;
            As[c4 * 4 + 1][arow] = v.y;
            As[c4 * 4 + 2][arow] = v.z;
            As[c4 * 4 + 3][arow] = v.w;
        }
        // stage both expert W tiles
        #pragma unroll
        for (int l = 0; l < 2; l++) {
            int kr = bkr + 8 * l;
            size_t goff = (size_t)(kt + kr) * D_MODEL + bn + bc4 * 4;
            *(float4*)&Bs[0][kr][bc4 * 4] = *(const float4*)(W1 + goff);
            *(float4*)&Bs[1][kr][bc4 * 4] = *(const float4*)(W2 + goff);
        }
        __syncthreads();

        if (uni >= 0) {
            // expert-uniform tile: shared B frag across all 8 rows
            const float (*B)[BN] = Bs[uni];
            #pragma unroll
            for (int k = 0; k < BK; k++) {
                float4 a0 = *(const float4*)&As[k][ty * 8];
                float4 a1 = *(const float4*)&As[k][ty * 8 + 4];
                float av[8] = {a0.x, a0.y, a0.z, a0.w, a1.x, a1.y, a1.z, a1.w};
                ulonglong2 bp0 = *(const ulonglong2*)&B[k][tx * 8];
                ulonglong2 bp1 = *(const ulonglong2*)&B[k][tx * 8 + 4];
                unsigned long long bv[4] = {bp0.x, bp0.y, bp1.x, bp1.y};
                #pragma unroll
                for (int m = 0; m < 8; m++) {
                    unsigned long long a2 = pack_dup(av[m]);
                    #pragma unroll
                    for (int n = 0; n < 4; n++)
                        FMA_F32X2(c2[m][n], a2, bv[n], c2[m][n]);
                }
            }
        } else {
            // boundary tile (straddles expert split): per-row W select
            #pragma unroll
            for (int k = 0; k < BK; k++) {
                float4 a0 = *(const float4*)&As[k][ty * 8];
                float4 a1 = *(const float4*)&As[k][ty * 8 + 4];
                float av[8] = {a0.x, a0.y, a0.z, a0.w, a1.x, a1.y, a1.z, a1.w};
                #pragma unroll
                for (int m = 0; m < 8; m++) {
                    const ulonglong2* bp =
                        (const ulonglong2*)&Bs[myrt[m]][k][tx * 8];
                    ulonglong2 q0 = bp[0], q1 = bp[1];
                    unsigned long long a2 = pack_dup(av[m]);
                    FMA_F32X2(c2[m][0], a2, q0.x, c2[m][0]);
                    FMA_F32X2(c2[m][1], a2, q0.y, c2[m][1]);
                    FMA_F32X2(c2[m][2], a2, q1.x, c2[m][2]);
                    FMA_F32X2(c2[m][3], a2, q1.y, c2[m][3]);
                }
            }
        }
        __syncthreads();
    }

    // epilogue: add per-expert bias, scatter rows back to original order
    #pragma unroll
    for (int m = 0; m < 8; m++) {
        const float* bb = myrt[m] ? b2 : b1;
        float4 bias0 = *(const float4*)(bb + bn + tx * 8);
        float4 bias1 = *(const float4*)(bb + bn + tx * 8 + 4);
        float r[8];
        #pragma unroll
        for (int n = 0; n < 4; n++) {
            unsigned long long v = c2[m][n];
            r[2 * n + 0] = __uint_as_float((unsigned int)(v & 0xffffffffu));
            r[2 * n + 1] = __uint_as_float((unsigned int)(v >> 32));
        }
        float4 o0 = make_float4(r[0] + bias0.x, r[1] + bias0.y,
                                r[2] + bias0.z, r[3] + bias0.w);
        float4 o1 = make_float4(r[4] + bias1.x, r[5] + bias1.y,
                                r[6] + bias1.z, r[7] + bias1.w);
        float* op = out + (size_t)myrow[m] * D_MODEL + bn + tx * 8;
        *(float4*)op       = o0;
        *(float4*)(op + 4) = o1;
    }
}

// ---------------- launch -----------------------------------------------------
extern "C" void kernel_launch(void* const* d_in, const int* in_sizes, int n_in,
                              void* d_out, int out_size)
{
    const float* x     = (const float*)d_in[0];
    const float* W1    = (const float*)d_in[1];
    const float* b1    = (const float*)d_in[2];
    const float* W2    = (const float*)d_in[3];
    const float* b2    = (const float*)d_in[4];
    const int*   route = (const int*)  d_in[5];
    float*       out   = (float*)d_out;

    k_reset<<<1, 1>>>();
    k_count<<<N_TOKENS / 256, 256>>>(route);
    k_init<<<1, 1>>>();
    k_scatter<<<N_TOKENS / 256, 256>>>(route);

    dim3 grid(D_MODEL / BN, N_TOKENS / BM);  // (8, 256)
    k_gemm<<<grid, NTHREADS>>>(x, W1, b1, W2, b2, route, out);
}

// round 3
// speedup vs baseline: 5.2733x; 5.2733x over previous
#include <cuda_runtime.h>
#include <cstdint>

#define N_TOKENS 32768
#define D_MODEL  1024
#define BM 128
#define BN 128
#define BK 32
#define KITERS (D_MODEL / BK)
#define NTHREADS 256
#define SMEM_BYTES 65536   // 2 stages x (16KB A + 16KB B)

// ---------------- device-global scratch ------------------------------------
__device__ int g_cnt0, g_c0, g_c1;
__device__ int g_perm[N_TOKENS];
__device__ float g_Wt[2][D_MODEL * (size_t)D_MODEL];   // Wt[e][n][k] = W_e[k][n], tf32-rounded

// ---------------- PTX helpers ----------------------------------------------
__device__ __forceinline__ uint32_t smem_u32(const void* p) {
    uint32_t a;
    asm("{ .reg .u64 t; cvta.to.shared.u64 t, %1; cvt.u32.u64 %0, t; }"
        : "=r"(a) : "l"(p));
    return a;
}

#define CP_ASYNC16(dst, gsrc) \
    asm volatile("cp.async.cg.shared.global [%0], [%1], 16;" \
                 :: "r"(dst), "l"(gsrc) : "memory")
#define CP_COMMIT() asm volatile("cp.async.commit_group;" ::: "memory")
#define CP_WAIT(n)  asm volatile("cp.async.wait_group %0;" :: "n"(n) : "memory")

#define MMA_TF32(c, a, b)                                                      \
    asm volatile("mma.sync.aligned.m16n8k8.row.col.f32.tf32.tf32.f32 "        \
                 "{%0,%1,%2,%3}, {%4,%5,%6,%7}, {%8,%9}, {%0,%1,%2,%3};"      \
                 : "+f"((c)[0]), "+f"((c)[1]), "+f"((c)[2]), "+f"((c)[3])     \
                 : "r"((a)[0]), "r"((a)[1]), "r"((a)[2]), "r"((a)[3]),        \
                   "r"((b)[0]), "r"((b)[1]))

// ---------------- sort-by-expert pipeline -----------------------------------
__global__ void k_reset() { g_cnt0 = 0; }

__global__ void k_count(const int* __restrict__ route) {
    __shared__ int ws[8];
    int i = blockIdx.x * blockDim.x + threadIdx.x;
    int v = (route[i] == 0) ? 1 : 0;
    #pragma unroll
    for (int o = 16; o > 0; o >>= 1) v += __shfl_down_sync(0xffffffffu, v, o);
    if ((threadIdx.x & 31) == 0) ws[threadIdx.x >> 5] = v;
    __syncthreads();
    if (threadIdx.x == 0) {
        int s = 0;
        #pragma unroll
        for (int j = 0; j < 8; j++) s += ws[j];
        atomicAdd(&g_cnt0, s);
    }
}

__global__ void k_init() { g_c0 = 0; g_c1 = g_cnt0; }

__global__ void k_scatter(const int* __restrict__ route) {
    int i = blockIdx.x * blockDim.x + threadIdx.x;
    int slot = (route[i] == 0) ? atomicAdd(&g_c0, 1) : atomicAdd(&g_c1, 1);
    g_perm[slot] = i;
}

// -------- weight transpose + tf32 rna rounding: g_Wt[e][n][k] = W_e[k][n] ----
__global__ void k_transpose(const float* __restrict__ W1, const float* __restrict__ W2) {
    __shared__ float t[32][33];
    int e = blockIdx.z;
    const float* W = e ? W2 : W1;
    float* Wt = g_Wt[e];
    int n0 = blockIdx.x * 32, k0 = blockIdx.y * 32;
    int tx = threadIdx.x, ty = threadIdx.y;   // block (32, 8)
    #pragma unroll
    for (int i = 0; i < 4; i++) {
        float v = W[(size_t)(k0 + ty + i * 8) * D_MODEL + n0 + tx];
        uint32_t u;
        asm("cvt.rna.tf32.f32 %0, %1;" : "=r"(u) : "f"(v));
        t[ty + i * 8][tx] = __uint_as_float(u);
    }
    __syncthreads();
    #pragma unroll
    for (int i = 0; i < 4; i++)
        Wt[(size_t)(n0 + ty + i * 8) * D_MODEL + k0 + tx] = t[tx][ty + i * 8];
}

// ---------------- tf32 mma.sync GEMM -----------------------------------------
// Dynamic smem: stage s A at s*16384, B at 32768 + s*16384.
// Tile layout: row r (128B = 8 x 16B groups), group c4 stored at c4 ^ (r & 7).
__global__ __launch_bounds__(NTHREADS, 2)
void k_gemm(const float* __restrict__ x, const float* __restrict__ b1,
            const float* __restrict__ b2, float* __restrict__ out)
{
    extern __shared__ __align__(128) char smem[];
    __shared__ int   srow[BM];
    __shared__ int   srt[BM];
    __shared__ float sbias[2][BN];

    const uint32_t sb  = smem_u32(smem);
    const int tid  = threadIdx.x;
    const int lane = tid & 31, wid = tid >> 5;
    const int tig  = lane & 3, gid = lane >> 2;
    const int wm   = wid >> 2, wn = wid & 3;          // warp tile 64m x 32n
    const int bn   = blockIdx.x * BN, bm = blockIdx.y * BM;

    const int cnt0 = g_cnt0;
    if (tid < BM) {
        srow[tid] = g_perm[bm + tid];
        srt[tid]  = (bm + tid < cnt0) ? 0 : 1;
    }
    if (tid < 128) sbias[0][tid] = b1[bn + tid];
    else           sbias[1][tid - 128] = b2[bn + tid - 128];
    __syncthreads();

    const int uni   = (srt[0] == srt[BM - 1]) ? srt[0] : -1;
    const int npass = (uni >= 0) ? 1 : 2;

    // staging map: chunk ch = tid + 256*j  ->  row ch>>3, 16B-group ch&7
    uint32_t dsw[4];
    uint64_t asrc[4];
    size_t   bofs[4];
    #pragma unroll
    for (int j = 0; j < 4; j++) {
        int ch = tid + NTHREADS * j;
        int r = ch >> 3, c4 = ch & 7;
        dsw[j]  = (uint32_t)((r * 8 + (c4 ^ (r & 7))) << 4);
        asrc[j] = __cvta_generic_to_global(x + (size_t)srow[r] * D_MODEL + c4 * 4);
        bofs[j] = (size_t)(bn + r) * D_MODEL + c4 * 4;
    }

    for (int pass = 0; pass < npass; pass++) {
        const int pe = (uni >= 0) ? uni : pass;
        const float* Wt = g_Wt[pe];
        uint64_t bsrc[4];
        #pragma unroll
        for (int j = 0; j < 4; j++)
            bsrc[j] = __cvta_generic_to_global(Wt + bofs[j]);

        float acc[4][4][4];
        #pragma unroll
        for (int mt = 0; mt < 4; mt++)
            #pragma unroll
            for (int nt = 0; nt < 4; nt++)
                #pragma unroll
                for (int q = 0; q < 4; q++) acc[mt][nt][q] = 0.f;

        // prologue: stage 0
        #pragma unroll
        for (int j = 0; j < 4; j++) {
            CP_ASYNC16(sb + dsw[j],         asrc[j]);
            CP_ASYNC16(sb + 32768 + dsw[j], bsrc[j]);
        }
        CP_COMMIT();

        for (int it = 0; it < KITERS; it++) {
            const int s = it & 1;
            if (it + 1 < KITERS) {
                const uint32_t so = (uint32_t)((s ^ 1) * 16384);
                const uint64_t ko = (uint64_t)(it + 1) * BK * 4;
                #pragma unroll
                for (int j = 0; j < 4; j++) {
                    CP_ASYNC16(sb + so + dsw[j],         asrc[j] + ko);
                    CP_ASYNC16(sb + 32768 + so + dsw[j], bsrc[j] + ko);
                }
                CP_COMMIT();
                CP_WAIT(1);
            } else {
                CP_WAIT(0);
            }
            __syncthreads();

            const char* As = smem + s * 16384;
            const char* Bs = smem + 32768 + s * 16384;
            #pragma unroll
            for (int kk = 0; kk < 4; kk++) {
                const int c4l = (2 * kk) ^ gid, c4h = (2 * kk + 1) ^ gid;
                uint32_t a[4][4], b[4][2];
                #pragma unroll
                for (int mt = 0; mt < 4; mt++) {
                    const int r0 = wm * 64 + mt * 16 + gid;
                    a[mt][0] = *(const uint32_t*)(As + r0 * 128       + (c4l << 4) + tig * 4);
                    a[mt][1] = *(const uint32_t*)(As + (r0 + 8) * 128 + (c4l << 4) + tig * 4);
                    a[mt][2] = *(const uint32_t*)(As + r0 * 128       + (c4h << 4) + tig * 4);
                    a[mt][3] = *(const uint32_t*)(As + (r0 + 8) * 128 + (c4h << 4) + tig * 4);
                }
                #pragma unroll
                for (int nt = 0; nt < 4; nt++) {
                    const int n0 = wn * 32 + nt * 8 + gid;
                    b[nt][0] = *(const uint32_t*)(Bs + n0 * 128 + (c4l << 4) + tig * 4);
                    b[nt][1] = *(const uint32_t*)(Bs + n0 * 128 + (c4h << 4) + tig * 4);
                }
                #pragma unroll
                for (int mt = 0; mt < 4; mt++)
                    #pragma unroll
                    for (int nt = 0; nt < 4; nt++)
                        MMA_TF32(acc[mt][nt], a[mt], b[nt]);
            }
            __syncthreads();
        }

        // epilogue: bias + scatter to original token rows (predicated per row)
        #pragma unroll
        for (int mt = 0; mt < 4; mt++) {
            #pragma unroll
            for (int h = 0; h < 2; h++) {
                const int rr = wm * 64 + mt * 16 + gid + h * 8;
                if (uni >= 0 || srt[rr] == pe) {
                    float* op = out + (size_t)srow[rr] * D_MODEL + bn;
                    #pragma unroll
                    for (int nt = 0; nt < 4; nt++) {
                        const int c = wn * 32 + nt * 8 + 2 * tig;
                        float2 v;
                        v.x = acc[mt][nt][h * 2 + 0] + sbias[pe][c];
                        v.y = acc[mt][nt][h * 2 + 1] + sbias[pe][c + 1];
                        *(float2*)(op + c) = v;
                    }
                }
            }
        }
        if (pass + 1 < npass) __syncthreads();
    }
}

// ---------------- launch -----------------------------------------------------
extern "C" void kernel_launch(void* const* d_in, const int* in_sizes, int n_in,
                              void* d_out, int out_size)
{
    const float* x     = (const float*)d_in[0];
    const float* W1    = (const float*)d_in[1];
    const float* b1    = (const float*)d_in[2];
    const float* W2    = (const float*)d_in[3];
    const float* b2    = (const float*)d_in[4];
    const int*   route = (const int*)  d_in[5];
    float*       out   = (float*)d_out;

    cudaFuncSetAttribute(k_gemm, cudaFuncAttributeMaxDynamicSharedMemorySize,
                         SMEM_BYTES);

    k_reset<<<1, 1>>>();
    k_count<<<N_TOKENS / 256, 256>>>(route);
    k_init<<<1, 1>>>();
    k_scatter<<<N_TOKENS / 256, 256>>>(route);
    k_transpose<<<dim3(32, 32, 2), dim3(32, 8)>>>(W1, W2);

    dim3 grid(D_MODEL / BN, N_TOKENS / BM);   // (8, 256)
    k_gemm<<<grid, NTHREADS, SMEM_BYTES>>>(x, b1, b2, out);
}

// round 4
// speedup vs baseline: 6.0571x; 1.1486x over previous
#include <cuda_runtime.h>
#include <cstdint>

#define N_TOKENS 32768
#define D_MODEL  1024
#define BM 128
#define BN 128
#define BK 32
#define KITERS (D_MODEL / BK)
#define NTHREADS 256
#define STAGE_BYTES 32768
#define SMEM_BYTES (3 * STAGE_BYTES)   // 3 stages x (16KB A + 16KB B)

// ---------------- device-global scratch ------------------------------------
__device__ int g_cnt0, g_c0, g_c1;
__device__ int g_perm[N_TOKENS];
__device__ float g_Wt[2][D_MODEL * (size_t)D_MODEL];   // Wt[e][n][k] = W_e[k][n], tf32-rounded

// ---------------- PTX helpers ----------------------------------------------
__device__ __forceinline__ uint32_t smem_u32(const void* p) {
    uint32_t a;
    asm("{ .reg .u64 t; cvta.to.shared.u64 t, %1; cvt.u32.u64 %0, t; }"
        : "=r"(a) : "l"(p));
    return a;
}

#define CP_ASYNC16(dst, gsrc) \
    asm volatile("cp.async.cg.shared.global [%0], [%1], 16;" \
                 :: "r"(dst), "l"(gsrc) : "memory")
#define CP_COMMIT() asm volatile("cp.async.commit_group;" ::: "memory")
#define CP_WAIT(n)  asm volatile("cp.async.wait_group %0;" :: "n"(n) : "memory")

#define LDSM_X4(r0, r1, r2, r3, addr)                                          \
    asm volatile("ldmatrix.sync.aligned.m8n8.x4.shared.b16 {%0,%1,%2,%3}, [%4];" \
                 : "=r"(r0), "=r"(r1), "=r"(r2), "=r"(r3) : "r"(addr))

#define MMA_TF32(c, a, b)                                                      \
    asm volatile("mma.sync.aligned.m16n8k8.row.col.f32.tf32.tf32.f32 "        \
                 "{%0,%1,%2,%3}, {%4,%5,%6,%7}, {%8,%9}, {%0,%1,%2,%3};"      \
                 : "+f"((c)[0]), "+f"((c)[1]), "+f"((c)[2]), "+f"((c)[3])     \
                 : "r"((a)[0]), "r"((a)[1]), "r"((a)[2]), "r"((a)[3]),        \
                   "r"((b)[0]), "r"((b)[1]))

// ---------------- sort-by-expert pipeline -----------------------------------
__global__ void k_reset() { g_cnt0 = 0; }

__global__ void k_count(const int* __restrict__ route) {
    __shared__ int ws[8];
    int i = blockIdx.x * blockDim.x + threadIdx.x;
    int v = (route[i] == 0) ? 1 : 0;
    #pragma unroll
    for (int o = 16; o > 0; o >>= 1) v += __shfl_down_sync(0xffffffffu, v, o);
    if ((threadIdx.x & 31) == 0) ws[threadIdx.x >> 5] = v;
    __syncthreads();
    if (threadIdx.x == 0) {
        int s = 0;
        #pragma unroll
        for (int j = 0; j < 8; j++) s += ws[j];
        atomicAdd(&g_cnt0, s);
    }
}

__global__ void k_init() { g_c0 = 0; g_c1 = g_cnt0; }

__global__ void k_scatter(const int* __restrict__ route) {
    int i = blockIdx.x * blockDim.x + threadIdx.x;
    int slot = (route[i] == 0) ? atomicAdd(&g_c0, 1) : atomicAdd(&g_c1, 1);
    g_perm[slot] = i;
}

// -------- weight transpose + tf32 rna rounding: g_Wt[e][n][k] = W_e[k][n] ----
__global__ void k_transpose(const float* __restrict__ W1, const float* __restrict__ W2) {
    __shared__ float t[32][33];
    int e = blockIdx.z;
    const float* W = e ? W2 : W1;
    float* Wt = g_Wt[e];
    int n0 = blockIdx.x * 32, k0 = blockIdx.y * 32;
    int tx = threadIdx.x, ty = threadIdx.y;   // block (32, 8)
    #pragma unroll
    for (int i = 0; i < 4; i++) {
        float v = W[(size_t)(k0 + ty + i * 8) * D_MODEL + n0 + tx];
        uint32_t u;
        asm("cvt.rna.tf32.f32 %0, %1;" : "=r"(u) : "f"(v));
        t[ty + i * 8][tx] = __uint_as_float(u);
    }
    __syncthreads();
    #pragma unroll
    for (int i = 0; i < 4; i++)
        Wt[(size_t)(n0 + ty + i * 8) * D_MODEL + k0 + tx] = t[tx][ty + i * 8];
}

// ---------------- tf32 mma.sync GEMM -----------------------------------------
// Dynamic smem: stage s: A at s*32768, B at s*32768 + 16384.
// Tile row r = 128B = 8 x 16B groups; logical group c4 stored at (c4 ^ (r & 7)).
__global__ __launch_bounds__(NTHREADS, 2)
void k_gemm(const float* __restrict__ x, const float* __restrict__ b1,
            const float* __restrict__ b2, float* __restrict__ out)
{
    extern __shared__ __align__(128) char smem[];
    __shared__ int   srow[BM];
    __shared__ int   srt[BM];
    __shared__ float sbias[2][BN];

    const uint32_t sb  = smem_u32(smem);
    const int tid  = threadIdx.x;
    const int lane = tid & 31, wid = tid >> 5;
    const int tig  = lane & 3, gid = lane >> 2;
    const int wm   = wid >> 2, wn = wid & 3;          // warp tile 64m x 32n
    const int bn   = blockIdx.x * BN, bm = blockIdx.y * BM;

    const int cnt0 = g_cnt0;
    if (tid < BM) {
        srow[tid] = g_perm[bm + tid];
        srt[tid]  = (bm + tid < cnt0) ? 0 : 1;
    }
    if (tid < 128) sbias[0][tid] = b1[bn + tid];
    else           sbias[1][tid - 128] = b2[bn + tid - 128];
    __syncthreads();

    const int uni   = (srt[0] == srt[BM - 1]) ? srt[0] : -1;
    const int npass = (uni >= 0) ? 1 : 2;

    // ---- cp.async staging map: chunk ch = tid + 256*j -> row ch>>3, group ch&7
    uint32_t dsw[4];
    uint64_t asrc[4];
    size_t   bofs[4];
    #pragma unroll
    for (int j = 0; j < 4; j++) {
        int ch = tid + NTHREADS * j;
        int r = ch >> 3, c4 = ch & 7;
        dsw[j]  = (uint32_t)((r * 8 + (c4 ^ (r & 7))) << 4);
        asrc[j] = __cvta_generic_to_global(x + (size_t)srow[r] * D_MODEL + c4 * 4);
        bofs[j] = (size_t)(bn + r) * D_MODEL + c4 * 4;
    }

    // ---- ldmatrix per-lane addressing -------------------------------------
    // A x4 (per mt): matrices {rows 0-7 kgL, rows 8-15 kgL, rows 0-7 kgH, rows 8-15 kgH}
    //   lane -> matrix l>>3: rowadd = ((l>>3)&1)*8 + (l&7), kgadd = (l>>4)&1
    // B x4 (per nt-pair): {nt0 kgL, nt0 kgH, nt1 kgL, nt1 kgH}
    //   lane -> matrix l>>3: nt = (l>>4)&1, kgadd = (l>>3)&1, row = nt*8+... 
    const int x7 = lane & 7;
    const int kgaddA = (lane >> 4) & 1;
    const int kgaddB = (lane >> 3) & 1;
    uint32_t rowAoff[4];
    #pragma unroll
    for (int mt = 0; mt < 4; mt++)
        rowAoff[mt] = (uint32_t)((wm * 64 + mt * 16 + ((lane >> 3) & 1) * 8 + x7) * 128);
    uint32_t rowBoff[2];
    #pragma unroll
    for (int np = 0; np < 2; np++)
        rowBoff[np] = (uint32_t)((wn * 32 + (np * 2 + ((lane >> 4) & 1)) * 8 + x7) * 128);

    for (int pass = 0; pass < npass; pass++) {
        const int pe = (uni >= 0) ? uni : pass;
        const float* Wt = g_Wt[pe];
        uint64_t bsrc[4];
        #pragma unroll
        for (int j = 0; j < 4; j++)
            bsrc[j] = __cvta_generic_to_global(Wt + bofs[j]);

        float acc[4][4][4];
        #pragma unroll
        for (int mt = 0; mt < 4; mt++)
            #pragma unroll
            for (int nt = 0; nt < 4; nt++)
                #pragma unroll
                for (int q = 0; q < 4; q++) acc[mt][nt][q] = 0.f;

        // prologue: stages 0 and 1
        #pragma unroll
        for (int p = 0; p < 2; p++) {
            const uint32_t so = p * STAGE_BYTES;
            const uint64_t ko = (uint64_t)p * BK * 4;
            #pragma unroll
            for (int j = 0; j < 4; j++) {
                CP_ASYNC16(sb + so + dsw[j],         asrc[j] + ko);
                CP_ASYNC16(sb + so + 16384 + dsw[j], bsrc[j] + ko);
            }
            CP_COMMIT();
        }

        int slot = 0, nslot = 2;
        for (int it = 0; it < KITERS; it++) {
            if (it + 1 < KITERS) { CP_WAIT(1); } else { CP_WAIT(0); }
            __syncthreads();

            // issue stage it+2 into nslot
            if (it + 2 < KITERS) {
                const uint32_t so = (uint32_t)nslot * STAGE_BYTES;
                const uint64_t ko = (uint64_t)(it + 2) * BK * 4;
                #pragma unroll
                for (int j = 0; j < 4; j++) {
                    CP_ASYNC16(sb + so + dsw[j],         asrc[j] + ko);
                    CP_ASYNC16(sb + so + 16384 + dsw[j], bsrc[j] + ko);
                }
                CP_COMMIT();
            }

            const uint32_t As = sb + (uint32_t)slot * STAGE_BYTES;
            const uint32_t Bs = As + 16384;
            #pragma unroll
            for (int kk = 0; kk < 4; kk++) {
                const uint32_t koffA = (uint32_t)(((2 * kk + kgaddA) ^ x7) << 4);
                const uint32_t koffB = (uint32_t)(((2 * kk + kgaddB) ^ x7) << 4);
                uint32_t a[4][4], b[4][2];
                #pragma unroll
                for (int mt = 0; mt < 4; mt++)
                    LDSM_X4(a[mt][0], a[mt][1], a[mt][2], a[mt][3],
                            As + rowAoff[mt] + koffA);
                #pragma unroll
                for (int np = 0; np < 2; np++)
                    LDSM_X4(b[np * 2][0], b[np * 2][1], b[np * 2 + 1][0], b[np * 2 + 1][1],
                            Bs + rowBoff[np] + koffB);
                #pragma unroll
                for (int mt = 0; mt < 4; mt++)
                    #pragma unroll
                    for (int nt = 0; nt < 4; nt++)
                        MMA_TF32(acc[mt][nt], a[mt], b[nt]);
            }
            slot = (slot + 1) % 3;
            nslot = (nslot + 1) % 3;
        }

        // epilogue: bias + scatter to original token rows (predicated per row)
        __syncthreads();   // all reads of last stage done before next pass reuses smem
        #pragma unroll
        for (int mt = 0; mt < 4; mt++) {
            #pragma unroll
            for (int h = 0; h < 2; h++) {
                const int rr = wm * 64 + mt * 16 + gid + h * 8;
                if (uni >= 0 || srt[rr] == pe) {
                    float* op = out + (size_t)srow[rr] * D_MODEL + bn;
                    #pragma unroll
                    for (int nt = 0; nt < 4; nt++) {
                        const int c = wn * 32 + nt * 8 + 2 * tig;
                        float2 v;
                        v.x = acc[mt][nt][h * 2 + 0] + sbias[pe][c];
                        v.y = acc[mt][nt][h * 2 + 1] + sbias[pe][c + 1];
                        *(float2*)(op + c) = v;
                    }
                }
            }
        }
    }
}

// ---------------- launch -----------------------------------------------------
extern "C" void kernel_launch(void* const* d_in, const int* in_sizes, int n_in,
                              void* d_out, int out_size)
{
    const float* x     = (const float*)d_in[0];
    const float* W1    = (const float*)d_in[1];
    const float* b1    = (const float*)d_in[2];
    const float* W2    = (const float*)d_in[3];
    const float* b2    = (const float*)d_in[4];
    const int*   route = (const int*)  d_in[5];
    float*       out   = (float*)d_out;

    cudaFuncSetAttribute(k_gemm, cudaFuncAttributeMaxDynamicSharedMemorySize,
                         SMEM_BYTES);

    k_reset<<<1, 1>>>();
    k_count<<<N_TOKENS / 256, 256>>>(route);
    k_init<<<1, 1>>>();
    k_scatter<<<N_TOKENS / 256, 256>>>(route);
    k_transpose<<<dim3(32, 32, 2), dim3(32, 8)>>>(W1, W2);

    dim3 grid(D_MODEL / BN, N_TOKENS / BM);   // (8, 256)
    k_gemm<<<grid, NTHREADS, SMEM_BYTES>>>(x, b1, b2, out);
}